// round 4
// baseline (speedup 1.0000x reference)
#include <cuda_runtime.h>
#include <cstdint>

#define B_ 4
#define H_ 8
#define N_ 2048
#define D_ 64
#define KTOP 16
#define SCALE (1.0f/64.0f)

#define BK 16
#define NIT 32            // 512 / BK

// ---- scratch (allocation-free rule: __device__ global) ----
__device__ float g_z[(size_t)B_ * N_ * N_];

// ---------------------------------------------------------------------------
// packed f32x2 helpers (base sm_100-family PTX, no 'a' features)
// ---------------------------------------------------------------------------
__device__ __forceinline__ unsigned long long pack_dup(float a) {
    unsigned long long d;
    asm("mov.b64 %0, {%1, %1};" : "=l"(d) : "f"(a));
    return d;
}
__device__ __forceinline__ unsigned long long ffma2(unsigned long long a,
                                                    unsigned long long b,
                                                    unsigned long long c) {
    unsigned long long d;
    asm("fma.rn.f32x2 %0, %1, %2, %3;" : "=l"(d) : "l"(a), "l"(b), "l"(c));
    return d;
}
__device__ __forceinline__ float gumbel_of(float u) {
    return -logf(-logf(u + 1e-9f) + 1e-9f);
}

// ---------------------------------------------------------------------------
// Kernel 1: per-batch SGEMM with packed-f32x2 FMAs.
// z[n,m] = SCALE * sum_c Qc[n,c]*Kc[m,c] + gumbel(u)   (softmax is monotonic:
// skipped; threshold semantics preserved exactly).
// Tile 128x128, BK=16, 128 threads, 8x16 microtile (64 f32x2 accs/thread).
// ---------------------------------------------------------------------------
__global__ __launch_bounds__(128, 2) void gemm_f32x2_kernel(
    const float* __restrict__ q,
    const float* __restrict__ k,
    const float* __restrict__ u)
{
    __shared__ float As[BK][128];
    __shared__ float Bs[BK][128];

    const int tid = threadIdx.x;
    const int b  = blockIdx.z;
    const int m0 = blockIdx.x * 128;   // K rows (output cols)
    const int n0 = blockIdx.y * 128;   // Q rows

    const int tn = (tid >> 3) * 8;     // 0..120, i-dim (rows)
    const int tm = (tid & 7) * 16;     // 0..112, j-dim (cols)

    unsigned long long acc[8][8];      // [i][j2] -> cols (2*j2, 2*j2+1)
#pragma unroll
    for (int i = 0; i < 8; i++)
#pragma unroll
        for (int j = 0; j < 8; j++) acc[i][j] = 0ull;

    const size_t bbase = (size_t)b * H_ * N_ * D_;

    // prefetch iter 0 (thread tid owns one row of each tile: 16 floats each)
    float4 qa[4], kb[4];
    {
        const size_t g = bbase;        // h=0, dd=0
        const float* qp = q + g + (size_t)(n0 + tid) * D_;
        const float* kp = k + g + (size_t)(m0 + tid) * D_;
#pragma unroll
        for (int c4 = 0; c4 < 4; c4++) {
            qa[c4] = *(const float4*)(qp + c4 * 4);
            kb[c4] = *(const float4*)(kp + c4 * 4);
        }
    }

#pragma unroll 1
    for (int it = 0; it < NIT; it++) {
        __syncthreads();               // smem free (prev compute done)
        // store prefetched regs -> smem, transposed; conflict-free (lane=row)
#pragma unroll
        for (int c4 = 0; c4 < 4; c4++) {
            As[c4 * 4 + 0][tid] = qa[c4].x;
            As[c4 * 4 + 1][tid] = qa[c4].y;
            As[c4 * 4 + 2][tid] = qa[c4].z;
            As[c4 * 4 + 3][tid] = qa[c4].w;
            Bs[c4 * 4 + 0][tid] = kb[c4].x;
            Bs[c4 * 4 + 1][tid] = kb[c4].y;
            Bs[c4 * 4 + 2][tid] = kb[c4].z;
            Bs[c4 * 4 + 3][tid] = kb[c4].w;
        }
        __syncthreads();

        // prefetch next tile under compute
        if (it + 1 < NIT) {
            const int c0 = (it + 1) * BK;
            const int h  = c0 >> 6;
            const int dd = c0 & 63;
            const size_t g = bbase + (size_t)h * (N_ * D_) + dd;
            const float* qp = q + g + (size_t)(n0 + tid) * D_;
            const float* kp = k + g + (size_t)(m0 + tid) * D_;
#pragma unroll
            for (int c4 = 0; c4 < 4; c4++) {
                qa[c4] = *(const float4*)(qp + c4 * 4);
                kb[c4] = *(const float4*)(kp + c4 * 4);
            }
        }

#pragma unroll
        for (int kk = 0; kk < BK; kk++) {
            float a[8];
            *(float4*)(a)     = *(const float4*)(&As[kk][tn]);
            *(float4*)(a + 4) = *(const float4*)(&As[kk][tn + 4]);
            union { float4 v; unsigned long long u2[2]; } bu[4];
            bu[0].v = *(const float4*)(&Bs[kk][tm]);
            bu[1].v = *(const float4*)(&Bs[kk][tm + 4]);
            bu[2].v = *(const float4*)(&Bs[kk][tm + 8]);
            bu[3].v = *(const float4*)(&Bs[kk][tm + 12]);
            unsigned long long b2[8];
#pragma unroll
            for (int j = 0; j < 4; j++) { b2[2*j] = bu[j].u2[0]; b2[2*j+1] = bu[j].u2[1]; }
#pragma unroll
            for (int i = 0; i < 8; i++) {
                const unsigned long long ad = pack_dup(a[i]);
#pragma unroll
                for (int j = 0; j < 8; j++)
                    acc[i][j] = ffma2(ad, b2[j], acc[i][j]);
            }
        }
    }

    // Epilogue: z = acc*SCALE + gumbel(u)
    const size_t ubase = (size_t)b * N_ * N_;
#pragma unroll
    for (int i = 0; i < 8; i++) {
        const int n = n0 + tn + i;
        const float* accf = (const float*)acc[i];     // 16 contiguous cols
        const float* urow = u   + ubase + (size_t)n * N_ + (m0 + tm);
        float*       zrow = g_z + ubase + (size_t)n * N_ + (m0 + tm);
#pragma unroll
        for (int j4 = 0; j4 < 16; j4 += 4) {
            float4 uv = *(const float4*)(urow + j4);
            float4 zv;
            zv.x = accf[j4 + 0] * SCALE + gumbel_of(uv.x);
            zv.y = accf[j4 + 1] * SCALE + gumbel_of(uv.y);
            zv.z = accf[j4 + 2] * SCALE + gumbel_of(uv.z);
            zv.w = accf[j4 + 3] * SCALE + gumbel_of(uv.w);
            *(float4*)(zrow + j4) = zv;
        }
    }
}

// ---------------------------------------------------------------------------
// Kernel 2: exact per-row 16th-largest via register-resident radix select
// (4 x 8-bit passes, warp-shuffle suffix scan instead of serial 256-bin loop).
// ---------------------------------------------------------------------------
__device__ __forceinline__ uint32_t f2ord(float f) {
    uint32_t v = __float_as_uint(f);
    return (v & 0x80000000u) ? ~v : (v | 0x80000000u);
}

__global__ __launch_bounds__(256) void topk_mask_kernel(float* __restrict__ out)
{
    const int row = blockIdx.x;                 // 0 .. B_*N_-1
    const float* z = g_z + (size_t)row * N_;
    const int tid = threadIdx.x;

    __shared__ int      hist[256];
    __shared__ uint32_t s_prefix;
    __shared__ int      s_k;

    float4 v0 = *(const float4*)(z + tid * 4);
    float4 v1 = *(const float4*)(z + 1024 + tid * 4);
    uint32_t key[8];
    key[0] = f2ord(v0.x); key[1] = f2ord(v0.y); key[2] = f2ord(v0.z); key[3] = f2ord(v0.w);
    key[4] = f2ord(v1.x); key[5] = f2ord(v1.y); key[6] = f2ord(v1.z); key[7] = f2ord(v1.w);

    if (tid == 0) { s_prefix = 0u; s_k = KTOP; }

#pragma unroll
    for (int pass = 0; pass < 4; pass++) {
        const int shift = 24 - pass * 8;
        hist[tid] = 0;
        __syncthreads();
        const uint32_t pref  = s_prefix;
        const int      kneed = s_k;
        const uint32_t hmask = (pass == 0) ? 0u : (0xFFFFFFFFu << (shift + 8));
#pragma unroll
        for (int j = 0; j < 8; j++)
            if ((key[j] & hmask) == pref)
                atomicAdd(&hist[(key[j] >> shift) & 255], 1);
        __syncthreads();

        if (tid < 32) {
            const int base = tid * 8;
            int h[8], ssum = 0;
#pragma unroll
            for (int j = 0; j < 8; j++) { h[j] = hist[base + j]; ssum += h[j]; }
            int suf = ssum;
#pragma unroll
            for (int off = 1; off < 32; off <<= 1) {
                int t = __shfl_down_sync(0xffffffffu, suf, off);
                if (tid + off < 32) suf += t;
            }
            int sufn = __shfl_down_sync(0xffffffffu, suf, 1);
            if (tid == 31) sufn = 0;
            if (suf >= kneed && sufn < kneed) {
                int cum = sufn;
#pragma unroll
                for (int j = 7; j >= 0; j--) {
                    cum += h[j];
                    if (cum >= kneed) {
                        s_prefix = pref | ((uint32_t)(base + j) << shift);
                        s_k      = kneed - (cum - h[j]);
                        break;
                    }
                }
            }
        }
        __syncthreads();
    }

    const uint32_t th = s_prefix;               // exact 16th-largest key
    float4 o0, o1;
    o0.x = key[0] >= th ? 1.0f : 0.0f;  o0.y = key[1] >= th ? 1.0f : 0.0f;
    o0.z = key[2] >= th ? 1.0f : 0.0f;  o0.w = key[3] >= th ? 1.0f : 0.0f;
    o1.x = key[4] >= th ? 1.0f : 0.0f;  o1.y = key[5] >= th ? 1.0f : 0.0f;
    o1.z = key[6] >= th ? 1.0f : 0.0f;  o1.w = key[7] >= th ? 1.0f : 0.0f;
    *(float4*)(out + (size_t)row * N_ + tid * 4)        = o0;
    *(float4*)(out + (size_t)row * N_ + 1024 + tid * 4) = o1;
}

// ---------------------------------------------------------------------------
extern "C" void kernel_launch(void* const* d_in, const int* in_sizes, int n_in,
                              void* d_out, int out_size)
{
    const float* q = (const float*)d_in[0];
    const float* k = (const float*)d_in[1];
    const float* u = (const float*)d_in[2];
    float* out = (float*)d_out;

    dim3 grid(N_ / 128, N_ / 128, B_);          // 16 x 16 x 4 = 1024 CTAs
    gemm_f32x2_kernel<<<grid, 128>>>(q, k, u);
    topk_mask_kernel<<<B_ * N_, 256>>>(out);
}

// round 5
// speedup vs baseline: 2.1882x; 2.1882x over previous
#include <cuda_runtime.h>
#include <cuda_bf16.h>
#include <cstdint>

#define B_ 4
#define H_ 8
#define N_ 2048
#define D_ 64
#define KTOP 16
#define SCALE (1.0f/64.0f)

#define NIT 16            // 512 / BK, BK=32
#define STAGE_BYTES 32768 // A tile 16KB + B tile 16KB
#define SMEM_TOTAL (2 * STAGE_BYTES)

// ---- scratch (allocation-free rule: __device__ global) ----
__device__ float g_z[(size_t)B_ * N_ * N_];

// ---------------------------------------------------------------------------
// helpers
// ---------------------------------------------------------------------------
__device__ __forceinline__ uint32_t smem_to_u32(const void* p) {
    uint32_t a;
    asm("{ .reg .u64 t; cvta.to.shared.u64 t, %1; cvt.u32.u64 %0, t; }" : "=r"(a) : "l"(p));
    return a;
}
// tile row = 128B: chunks 0..7 of 16B (hi k0..31 -> chunks 0..3, lo -> 4..7),
// swizzled chunk = chunk ^ (row & 7)  (conflict-free for STS.128 and ldmatrix)
__device__ __forceinline__ uint32_t tile_off(int row, int chunk) {
    return (uint32_t)(row * 128 + ((chunk ^ (row & 7)) << 4));
}
__device__ __forceinline__ void ldsm4(uint32_t& r0, uint32_t& r1,
                                      uint32_t& r2, uint32_t& r3, uint32_t addr) {
    asm volatile("ldmatrix.sync.aligned.m8n8.x4.shared.b16 {%0,%1,%2,%3}, [%4];"
                 : "=r"(r0), "=r"(r1), "=r"(r2), "=r"(r3) : "r"(addr));
}
__device__ __forceinline__ void mma_bf16(float* c, const uint32_t* a,
                                         uint32_t b0, uint32_t b1) {
    asm volatile(
        "mma.sync.aligned.m16n8k16.row.col.f32.bf16.bf16.f32 "
        "{%0,%1,%2,%3}, {%4,%5,%6,%7}, {%8,%9}, {%0,%1,%2,%3};"
        : "+f"(c[0]), "+f"(c[1]), "+f"(c[2]), "+f"(c[3])
        : "r"(a[0]), "r"(a[1]), "r"(a[2]), "r"(a[3]), "r"(b0), "r"(b1));
}
__device__ __forceinline__ void cvt2(float a, float b, uint32_t& h, uint32_t& l) {
    __nv_bfloat16 ba = __float2bfloat16_rn(a), bb = __float2bfloat16_rn(b);
    float ra = a - __bfloat162float(ba);
    float rb = b - __bfloat162float(bb);
    __nv_bfloat16 la = __float2bfloat16_rn(ra), lb = __float2bfloat16_rn(rb);
    h = (uint32_t)__bfloat16_as_ushort(ba) | ((uint32_t)__bfloat16_as_ushort(bb) << 16);
    l = (uint32_t)__bfloat16_as_ushort(la) | ((uint32_t)__bfloat16_as_ushort(lb) << 16);
}
__device__ __forceinline__ float gumbel_of(float u) {
    return -logf(-logf(u + 1e-9f) + 1e-9f);
}

// ---------------------------------------------------------------------------
// Kernel 1: split-bf16 (3-term) mma.sync GEMM + gumbel epilogue -> g_z
// z[n,m] = SCALE * sum_c Qc[n,c]*Kc[m,c] + gumbel(u).  Softmax skipped
// (monotonic; threshold semantics preserved exactly).
// CTA tile 128x128, BK=32, 256 threads = 8 warps (4 m x 2 n), warp tile 32x64.
// ---------------------------------------------------------------------------
__global__ __launch_bounds__(256, 1) void gemm_mma_kernel(
    const float* __restrict__ q,
    const float* __restrict__ k,
    const float* __restrict__ u)
{
    extern __shared__ char smem[];
    const uint32_t sbase = smem_to_u32(smem);

    const int tid = threadIdx.x;
    const int lid = tid & 31;
    const int wid = tid >> 5;
    const int wm  = wid >> 1;          // 0..3 : m block (32 rows)
    const int wn  = wid & 1;           // 0..1 : n block (64 cols)

    const int b  = blockIdx.z;
    const int m0 = blockIdx.x * 128;   // z cols (K rows)
    const int n0 = blockIdx.y * 128;   // z rows (Q rows)

    const size_t bbase = (size_t)b * H_ * N_ * D_;

    // loader role: tid<128 -> A (Q rows), tid>=128 -> B (K rows); one row each
    const int lrow = tid & 127;
    const float* gsrc = (tid < 128 ? q : k) + bbase
                      + (size_t)((tid < 128 ? n0 : m0) + lrow) * D_;
    const uint32_t my_tile = (tid < 128) ? 0u : 16384u;

    float acc[2][8][4];
#pragma unroll
    for (int i = 0; i < 2; i++)
#pragma unroll
        for (int j = 0; j < 8; j++)
#pragma unroll
            for (int t = 0; t < 4; t++) acc[i][j][t] = 0.0f;

    // prefetch + convert iter 0 (row of 32 floats -> 16 hi u32 + 16 lo u32)
    uint32_t hi[16], lo[16];
    {
        const float4* ga = (const float4*)gsrc;   // it=0: h=0, dd=0
#pragma unroll
        for (int c4 = 0; c4 < 8; c4++) {
            float4 f = ga[c4];
            cvt2(f.x, f.y, hi[c4 * 2 + 0], lo[c4 * 2 + 0]);
            cvt2(f.z, f.w, hi[c4 * 2 + 1], lo[c4 * 2 + 1]);
        }
    }

    // ldmatrix lane addressing (constant per thread)
    const int ar = lid & 15;                       // A row-in-frag
    const int ac = lid >> 4;                       // A k-chunk sel
    const int br = (lid & 7) + ((lid >> 4) << 3);  // B row-in-frag (2 n8 blocks)
    const int bc = (lid >> 3) & 1;                 // B k-chunk sel

#pragma unroll 1
    for (int it = 0; it < NIT; it++) {
        const uint32_t stg = sbase + (uint32_t)(it & 1) * STAGE_BYTES;

        __syncthreads();   // stage (it&1) free: compute from it-2 done
        // store converted row to smem (conflict-free swizzle)
        {
            char* tb = smem + (it & 1) * STAGE_BYTES + my_tile;
#pragma unroll
            for (int c = 0; c < 4; c++) {
                *(uint4*)(tb + tile_off(lrow, c)) =
                    make_uint4(hi[c * 4], hi[c * 4 + 1], hi[c * 4 + 2], hi[c * 4 + 3]);
                *(uint4*)(tb + tile_off(lrow, 4 + c)) =
                    make_uint4(lo[c * 4], lo[c * 4 + 1], lo[c * 4 + 2], lo[c * 4 + 3]);
            }
        }
        __syncthreads();

        // prefetch + convert next iter
        if (it + 1 < NIT) {
            const int h  = (it + 1) >> 1;
            const int dd = ((it + 1) & 1) * 32;
            const float4* ga = (const float4*)(gsrc + (size_t)h * (N_ * D_) + dd);
#pragma unroll
            for (int c4 = 0; c4 < 8; c4++) {
                float4 f = ga[c4];
                cvt2(f.x, f.y, hi[c4 * 2 + 0], lo[c4 * 2 + 0]);
                cvt2(f.z, f.w, hi[c4 * 2 + 1], lo[c4 * 2 + 1]);
            }
        }

        const uint32_t abase = stg;
        const uint32_t bbase_s = stg + 16384u;

#pragma unroll
        for (int s = 0; s < 2; s++) {             // two k16 steps per BK=32
            uint32_t ah[2][4], al[2][4];
#pragma unroll
            for (int mf = 0; mf < 2; mf++) {
                const int arow = wm * 32 + mf * 16 + ar;
                ldsm4(ah[mf][0], ah[mf][1], ah[mf][2], ah[mf][3],
                      abase + tile_off(arow, s * 2 + ac));
                ldsm4(al[mf][0], al[mf][1], al[mf][2], al[mf][3],
                      abase + tile_off(arow, s * 2 + ac + 4));
            }
#pragma unroll
            for (int nf2 = 0; nf2 < 4; nf2++) {
                const int brow = wn * 64 + nf2 * 16 + br;
                uint32_t bh0, bh1, bh2, bh3, bl0, bl1, bl2, bl3;
                ldsm4(bh0, bh1, bh2, bh3, bbase_s + tile_off(brow, s * 2 + bc));
                ldsm4(bl0, bl1, bl2, bl3, bbase_s + tile_off(brow, s * 2 + bc + 4));
#pragma unroll
                for (int mf = 0; mf < 2; mf++) {
                    float* c0 = acc[mf][nf2 * 2 + 0];
                    float* c1 = acc[mf][nf2 * 2 + 1];
                    mma_bf16(c0, ah[mf], bh0, bh1);   // hi*hi
                    mma_bf16(c1, ah[mf], bh2, bh3);
                    mma_bf16(c0, ah[mf], bl0, bl1);   // hi*lo
                    mma_bf16(c1, ah[mf], bl2, bl3);
                    mma_bf16(c0, al[mf], bh0, bh1);   // lo*hi
                    mma_bf16(c1, al[mf], bh2, bh3);
                }
            }
        }
    }

    // Epilogue: z = acc*SCALE + gumbel(u) -> g_z (coalesced: 4 lanes x float2
    // cover one 32B sector)
    const int r4 = lid >> 2;
    const int c2 = (lid & 3) * 2;
#pragma unroll
    for (int mf = 0; mf < 2; mf++) {
#pragma unroll
        for (int rr = 0; rr < 2; rr++) {
            const int row = n0 + wm * 32 + mf * 16 + r4 + rr * 8;
            const size_t rbase = ((size_t)b * N_ + row) * N_ + m0 + wn * 64;
            const float* urow = u + rbase;
            float*       zrow = g_z + rbase;
#pragma unroll
            for (int j = 0; j < 8; j++) {
                const int co = (j >> 1) * 16 + (j & 1) * 8 + c2;
                float2 uv = *(const float2*)(urow + co);
                float2 zv;
                zv.x = acc[mf][j][rr * 2 + 0] * SCALE + gumbel_of(uv.x);
                zv.y = acc[mf][j][rr * 2 + 1] * SCALE + gumbel_of(uv.y);
                *(float2*)(zrow + co) = zv;
            }
        }
    }
}

// ---------------------------------------------------------------------------
// Kernel 2: exact per-row 16th-largest via register-resident radix select
// (4 x 8-bit passes, warp-shuffle suffix scan).
// ---------------------------------------------------------------------------
__device__ __forceinline__ uint32_t f2ord(float f) {
    uint32_t v = __float_as_uint(f);
    return (v & 0x80000000u) ? ~v : (v | 0x80000000u);
}

__global__ __launch_bounds__(256) void topk_mask_kernel(float* __restrict__ out)
{
    const int row = blockIdx.x;                 // 0 .. B_*N_-1
    const float* z = g_z + (size_t)row * N_;
    const int tid = threadIdx.x;

    __shared__ int      hist[256];
    __shared__ uint32_t s_prefix;
    __shared__ int      s_k;

    float4 v0 = *(const float4*)(z + tid * 4);
    float4 v1 = *(const float4*)(z + 1024 + tid * 4);
    uint32_t key[8];
    key[0] = f2ord(v0.x); key[1] = f2ord(v0.y); key[2] = f2ord(v0.z); key[3] = f2ord(v0.w);
    key[4] = f2ord(v1.x); key[5] = f2ord(v1.y); key[6] = f2ord(v1.z); key[7] = f2ord(v1.w);

    if (tid == 0) { s_prefix = 0u; s_k = KTOP; }

#pragma unroll
    for (int pass = 0; pass < 4; pass++) {
        const int shift = 24 - pass * 8;
        hist[tid] = 0;
        __syncthreads();
        const uint32_t pref  = s_prefix;
        const int      kneed = s_k;
        const uint32_t hmask = (pass == 0) ? 0u : (0xFFFFFFFFu << (shift + 8));
#pragma unroll
        for (int j = 0; j < 8; j++)
            if ((key[j] & hmask) == pref)
                atomicAdd(&hist[(key[j] >> shift) & 255], 1);
        __syncthreads();

        if (tid < 32) {
            const int base = tid * 8;
            int h[8], ssum = 0;
#pragma unroll
            for (int j = 0; j < 8; j++) { h[j] = hist[base + j]; ssum += h[j]; }
            int suf = ssum;
#pragma unroll
            for (int off = 1; off < 32; off <<= 1) {
                int t = __shfl_down_sync(0xffffffffu, suf, off);
                if (tid + off < 32) suf += t;
            }
            int sufn = __shfl_down_sync(0xffffffffu, suf, 1);
            if (tid == 31) sufn = 0;
            if (suf >= kneed && sufn < kneed) {
                int cum = sufn;
#pragma unroll
                for (int j = 7; j >= 0; j--) {
                    cum += h[j];
                    if (cum >= kneed) {
                        s_prefix = pref | ((uint32_t)(base + j) << shift);
                        s_k      = kneed - (cum - h[j]);
                        break;
                    }
                }
            }
        }
        __syncthreads();
    }

    const uint32_t th = s_prefix;               // exact 16th-largest key
    float4 o0, o1;
    o0.x = key[0] >= th ? 1.0f : 0.0f;  o0.y = key[1] >= th ? 1.0f : 0.0f;
    o0.z = key[2] >= th ? 1.0f : 0.0f;  o0.w = key[3] >= th ? 1.0f : 0.0f;
    o1.x = key[4] >= th ? 1.0f : 0.0f;  o1.y = key[5] >= th ? 1.0f : 0.0f;
    o1.z = key[6] >= th ? 1.0f : 0.0f;  o1.w = key[7] >= th ? 1.0f : 0.0f;
    *(float4*)(out + (size_t)row * N_ + tid * 4)        = o0;
    *(float4*)(out + (size_t)row * N_ + 1024 + tid * 4) = o1;
}

// ---------------------------------------------------------------------------
extern "C" void kernel_launch(void* const* d_in, const int* in_sizes, int n_in,
                              void* d_out, int out_size)
{
    const float* q = (const float*)d_in[0];
    const float* k = (const float*)d_in[1];
    const float* u = (const float*)d_in[2];
    float* out = (float*)d_out;

    cudaFuncSetAttribute(gemm_mma_kernel,
                         cudaFuncAttributeMaxDynamicSharedMemorySize, SMEM_TOTAL);

    dim3 grid(N_ / 128, N_ / 128, B_);          // 16 x 16 x 4 = 1024 CTAs
    gemm_mma_kernel<<<grid, 256, SMEM_TOTAL>>>(q, k, u);
    topk_mask_kernel<<<B_ * N_, 256>>>(out);
}

// round 6
// speedup vs baseline: 2.7852x; 1.2728x over previous
#include <cuda_runtime.h>
#include <cuda_bf16.h>
#include <cstdint>

#define B_ 4
#define H_ 8
#define N_ 2048
#define D_ 64
#define KTOP 16
#define SCALE (1.0f/64.0f)

#define NIT 16              // 512 / BK, BK=32
#define STAGE_BYTES 32768   // A tile 16KB + B tile 16KB
#define NSTAGE 3
#define SMEM_TOTAL (NSTAGE * STAGE_BYTES)

// ---- global scratch (allocation-free rule: __device__ globals) ----
__device__ float g_z[(size_t)B_ * N_ * N_];
// pre-split bf16 planes: [b][h][half][n][64]  (64 = 32 hi bf16 | 32 lo bf16 = 128B)
__device__ __nv_bfloat16 g_qs[(size_t)B_ * H_ * 2 * N_ * 64];
__device__ __nv_bfloat16 g_ks[(size_t)B_ * H_ * 2 * N_ * 64];

// ---------------------------------------------------------------------------
// helpers
// ---------------------------------------------------------------------------
__device__ __forceinline__ uint32_t smem_to_u32(const void* p) {
    uint32_t a;
    asm("{ .reg .u64 t; cvta.to.shared.u64 t, %1; cvt.u32.u64 %0, t; }" : "=r"(a) : "l"(p));
    return a;
}
// tile row = 128B, 8 chunks of 16B; swizzled chunk = chunk ^ (row & 7)
__device__ __forceinline__ uint32_t tile_off(int row, int chunk) {
    return (uint32_t)(row * 128 + ((chunk ^ (row & 7)) << 4));
}
__device__ __forceinline__ void cp16(uint32_t dst, const void* src) {
    asm volatile("cp.async.cg.shared.global [%0], [%1], 16;" :: "r"(dst), "l"(src) : "memory");
}
__device__ __forceinline__ void cp_commit() {
    asm volatile("cp.async.commit_group;" ::: "memory");
}
template<int Ng> __device__ __forceinline__ void cp_wait() {
    asm volatile("cp.async.wait_group %0;" :: "n"(Ng) : "memory");
}
__device__ __forceinline__ void ldsm4(uint32_t* r, uint32_t addr) {
    asm volatile("ldmatrix.sync.aligned.m8n8.x4.shared.b16 {%0,%1,%2,%3}, [%4];"
                 : "=r"(r[0]), "=r"(r[1]), "=r"(r[2]), "=r"(r[3]) : "r"(addr));
}
__device__ __forceinline__ void mma_bf16(float* c, const uint32_t* a,
                                         uint32_t b0, uint32_t b1) {
    asm volatile(
        "mma.sync.aligned.m16n8k16.row.col.f32.bf16.bf16.f32 "
        "{%0,%1,%2,%3}, {%4,%5,%6,%7}, {%8,%9}, {%0,%1,%2,%3};"
        : "+f"(c[0]), "+f"(c[1]), "+f"(c[2]), "+f"(c[3])
        : "r"(a[0]), "r"(a[1]), "r"(a[2]), "r"(a[3]), "r"(b0), "r"(b1));
}
__device__ __forceinline__ float gumbel_of(float u) {
    return -logf(-logf(u + 1e-9f) + 1e-9f);
}

// ---------------------------------------------------------------------------
// Kernel 0: split fp32 -> (hi, lo) bf16 planes in GEMM tile-row format.
// grid (4096, 2): y==0 -> q, y==1 -> k. Each thread: one aligned float4.
// ---------------------------------------------------------------------------
__global__ __launch_bounds__(256) void split_kernel(
    const float* __restrict__ q, const float* __restrict__ k)
{
    const int f = blockIdx.x * 256 + threadIdx.x;       // float4 index
    const size_t e = (size_t)f * 4;
    const int d    = (int)(e & 63);
    const int n    = (int)((e >> 6) & 2047);
    const int hb   = (int)(e >> 17);                    // b*8 + h
    const int half = d >> 5;
    const int pos  = d & 31;

    const float* src = blockIdx.y ? k : q;
    __nv_bfloat16* dst = blockIdx.y ? g_ks : g_qs;

    float4 v = *(const float4*)(src + e);
    const float fv[4] = {v.x, v.y, v.z, v.w};
    ushort hi[4], lo[4];
#pragma unroll
    for (int j = 0; j < 4; j++) {
        __nv_bfloat16 h = __float2bfloat16_rn(fv[j]);
        __nv_bfloat16 l = __float2bfloat16_rn(fv[j] - __bfloat162float(h));
        hi[j] = __bfloat16_as_ushort(h);
        lo[j] = __bfloat16_as_ushort(l);
    }
    __nv_bfloat16* row = dst + ((size_t)(hb * 2 + half) * N_ + n) * 64;
    *(uint2*)((ushort*)row + pos)      = make_uint2(
        (uint32_t)hi[0] | ((uint32_t)hi[1] << 16),
        (uint32_t)hi[2] | ((uint32_t)hi[3] << 16));
    *(uint2*)((ushort*)row + 32 + pos) = make_uint2(
        (uint32_t)lo[0] | ((uint32_t)lo[1] << 16),
        (uint32_t)lo[2] | ((uint32_t)lo[3] << 16));
}

// ---------------------------------------------------------------------------
// Kernel 1: split-bf16 (3-term) mma.sync GEMM + gumbel epilogue -> g_z
// CTA tile 128x128, BK=32, 256 threads = 8 warps (4m x 2n), warp tile 32x64.
// cp.async 3-stage pipeline, term-major MMA ordering.
// ---------------------------------------------------------------------------
__global__ __launch_bounds__(256, 1) void gemm_mma_kernel(
    const float* __restrict__ u)
{
    extern __shared__ char smem[];
    const uint32_t sbase = smem_to_u32(smem);

    const int tid = threadIdx.x;
    const int lid = tid & 31;
    const int wid = tid >> 5;
    const int wm  = wid >> 1;          // 0..3 : m block (32 rows)
    const int wn  = wid & 1;           // 0..1 : n block (64 cols)

    const int b  = blockIdx.z;
    const int m0 = blockIdx.x * 128;   // z cols (K rows)
    const int n0 = blockIdx.y * 128;   // z rows (Q rows)

    // loader: tid<128 -> A rows (from g_qs), else B rows (from g_ks)
    const int lrow = tid & 127;
    const __nv_bfloat16* lsrc0 = (tid < 128)
        ? g_qs + ((size_t)(b * H_ * 2) * N_ + (n0 + lrow)) * 64
        : g_ks + ((size_t)(b * H_ * 2) * N_ + (m0 + lrow)) * 64;
    const uint32_t my_tile = (tid < 128) ? 0u : 16384u;
    const size_t plane = (size_t)N_ * 64;          // bf16 per (h,half) plane

    float acc[2][8][4];
#pragma unroll
    for (int i = 0; i < 2; i++)
#pragma unroll
        for (int j = 0; j < 8; j++)
#pragma unroll
            for (int t = 0; t < 4; t++) acc[i][j][t] = 0.0f;

    // ldmatrix lane addressing
    const int ar = lid & 15;
    const int ac = lid >> 4;
    const int br = (lid & 7) + ((lid >> 4) << 3);
    const int bc = (lid >> 3) & 1;

    // prologue: stage 0
    {
        const __nv_bfloat16* src = lsrc0;   // it=0 -> plane 0
        const uint32_t dbase = sbase + my_tile;
#pragma unroll
        for (int c = 0; c < 8; c++)
            cp16(dbase + tile_off(lrow, c), (const char*)src + c * 16);
        cp_commit();
    }

#pragma unroll 1
    for (int it = 0; it < NIT; it++) {
        const int stg = it % NSTAGE;
        if (it + 1 < NIT) {
            const __nv_bfloat16* src = lsrc0 + (size_t)(it + 1) * plane;
            const uint32_t dbase = sbase + (uint32_t)(((it + 1) % NSTAGE) * STAGE_BYTES) + my_tile;
#pragma unroll
            for (int c = 0; c < 8; c++)
                cp16(dbase + tile_off(lrow, c), (const char*)src + c * 16);
            cp_commit();
            cp_wait<1>();
        } else {
            cp_wait<0>();
        }
        __syncthreads();

        const uint32_t abase   = sbase + (uint32_t)(stg * STAGE_BYTES);
        const uint32_t bbase_s = abase + 16384u;

#pragma unroll
        for (int s = 0; s < 2; s++) {
            uint32_t ah[2][4], al[2][4], bh[4][4], bl[4][4];
#pragma unroll
            for (int mf = 0; mf < 2; mf++) {
                const int arow = wm * 32 + mf * 16 + ar;
                ldsm4(ah[mf], abase + tile_off(arow, s * 2 + ac));
                ldsm4(al[mf], abase + tile_off(arow, s * 2 + ac + 4));
            }
#pragma unroll
            for (int nf = 0; nf < 4; nf++) {
                const int brow = wn * 64 + nf * 16 + br;
                ldsm4(bh[nf], bbase_s + tile_off(brow, s * 2 + bc));
                ldsm4(bl[nf], bbase_s + tile_off(brow, s * 2 + bc + 4));
            }
            // term-major: 16 independent MMAs per term, same-acc distance = 16
#pragma unroll
            for (int nf = 0; nf < 4; nf++)
#pragma unroll
                for (int mf = 0; mf < 2; mf++) {
                    mma_bf16(acc[mf][nf * 2 + 0], ah[mf], bh[nf][0], bh[nf][1]);
                    mma_bf16(acc[mf][nf * 2 + 1], ah[mf], bh[nf][2], bh[nf][3]);
                }
#pragma unroll
            for (int nf = 0; nf < 4; nf++)
#pragma unroll
                for (int mf = 0; mf < 2; mf++) {
                    mma_bf16(acc[mf][nf * 2 + 0], ah[mf], bl[nf][0], bl[nf][1]);
                    mma_bf16(acc[mf][nf * 2 + 1], ah[mf], bl[nf][2], bl[nf][3]);
                }
#pragma unroll
            for (int nf = 0; nf < 4; nf++)
#pragma unroll
                for (int mf = 0; mf < 2; mf++) {
                    mma_bf16(acc[mf][nf * 2 + 0], al[mf], bh[nf][0], bh[nf][1]);
                    mma_bf16(acc[mf][nf * 2 + 1], al[mf], bh[nf][2], bh[nf][3]);
                }
        }
    }

    // Epilogue: z = acc*SCALE + gumbel(u) -> g_z
    const int r4 = lid >> 2;
    const int c2 = (lid & 3) * 2;
#pragma unroll
    for (int mf = 0; mf < 2; mf++) {
#pragma unroll
        for (int rr = 0; rr < 2; rr++) {
            const int row = n0 + wm * 32 + mf * 16 + r4 + rr * 8;
            const size_t rbase = ((size_t)b * N_ + row) * N_ + m0 + wn * 64;
            const float* urow = u + rbase;
            float*       zrow = g_z + rbase;
#pragma unroll
            for (int j = 0; j < 8; j++) {
                const int co = (j >> 1) * 16 + (j & 1) * 8 + c2;
                float2 uv = *(const float2*)(urow + co);
                float2 zv;
                zv.x = acc[mf][j][rr * 2 + 0] * SCALE + gumbel_of(uv.x);
                zv.y = acc[mf][j][rr * 2 + 1] * SCALE + gumbel_of(uv.y);
                *(float2*)(zrow + co) = zv;
            }
        }
    }
}

// ---------------------------------------------------------------------------
// Kernel 2: exact per-row 16th-largest via register-resident radix select.
// ---------------------------------------------------------------------------
__device__ __forceinline__ uint32_t f2ord(float f) {
    uint32_t v = __float_as_uint(f);
    return (v & 0x80000000u) ? ~v : (v | 0x80000000u);
}

__global__ __launch_bounds__(256) void topk_mask_kernel(float* __restrict__ out)
{
    const int row = blockIdx.x;
    const float* z = g_z + (size_t)row * N_;
    const int tid = threadIdx.x;

    __shared__ int      hist[256];
    __shared__ uint32_t s_prefix;
    __shared__ int      s_k;

    float4 v0 = *(const float4*)(z + tid * 4);
    float4 v1 = *(const float4*)(z + 1024 + tid * 4);
    uint32_t key[8];
    key[0] = f2ord(v0.x); key[1] = f2ord(v0.y); key[2] = f2ord(v0.z); key[3] = f2ord(v0.w);
    key[4] = f2ord(v1.x); key[5] = f2ord(v1.y); key[6] = f2ord(v1.z); key[7] = f2ord(v1.w);

    if (tid == 0) { s_prefix = 0u; s_k = KTOP; }

#pragma unroll
    for (int pass = 0; pass < 4; pass++) {
        const int shift = 24 - pass * 8;
        hist[tid] = 0;
        __syncthreads();
        const uint32_t pref  = s_prefix;
        const int      kneed = s_k;
        const uint32_t hmask = (pass == 0) ? 0u : (0xFFFFFFFFu << (shift + 8));
#pragma unroll
        for (int j = 0; j < 8; j++)
            if ((key[j] & hmask) == pref)
                atomicAdd(&hist[(key[j] >> shift) & 255], 1);
        __syncthreads();

        if (tid < 32) {
            const int base = tid * 8;
            int h[8], ssum = 0;
#pragma unroll
            for (int j = 0; j < 8; j++) { h[j] = hist[base + j]; ssum += h[j]; }
            int suf = ssum;
#pragma unroll
            for (int off = 1; off < 32; off <<= 1) {
                int t = __shfl_down_sync(0xffffffffu, suf, off);
                if (tid + off < 32) suf += t;
            }
            int sufn = __shfl_down_sync(0xffffffffu, suf, 1);
            if (tid == 31) sufn = 0;
            if (suf >= kneed && sufn < kneed) {
                int cum = sufn;
#pragma unroll
                for (int j = 7; j >= 0; j--) {
                    cum += h[j];
                    if (cum >= kneed) {
                        s_prefix = pref | ((uint32_t)(base + j) << shift);
                        s_k      = kneed - (cum - h[j]);
                        break;
                    }
                }
            }
        }
        __syncthreads();
    }

    const uint32_t th = s_prefix;
    float4 o0, o1;
    o0.x = key[0] >= th ? 1.0f : 0.0f;  o0.y = key[1] >= th ? 1.0f : 0.0f;
    o0.z = key[2] >= th ? 1.0f : 0.0f;  o0.w = key[3] >= th ? 1.0f : 0.0f;
    o1.x = key[4] >= th ? 1.0f : 0.0f;  o1.y = key[5] >= th ? 1.0f : 0.0f;
    o1.z = key[6] >= th ? 1.0f : 0.0f;  o1.w = key[7] >= th ? 1.0f : 0.0f;
    *(float4*)(out + (size_t)row * N_ + tid * 4)        = o0;
    *(float4*)(out + (size_t)row * N_ + 1024 + tid * 4) = o1;
}

// ---------------------------------------------------------------------------
extern "C" void kernel_launch(void* const* d_in, const int* in_sizes, int n_in,
                              void* d_out, int out_size)
{
    const float* q = (const float*)d_in[0];
    const float* k = (const float*)d_in[1];
    const float* u = (const float*)d_in[2];
    float* out = (float*)d_out;

    cudaFuncSetAttribute(gemm_mma_kernel,
                         cudaFuncAttributeMaxDynamicSharedMemorySize, SMEM_TOTAL);

    dim3 sgrid(4096, 2);
    split_kernel<<<sgrid, 256>>>(q, k);
    dim3 grid(N_ / 128, N_ / 128, B_);
    gemm_mma_kernel<<<grid, 256, SMEM_TOTAL>>>(u);
    topk_mask_kernel<<<B_ * N_, 256>>>(out);
}

// round 8
// speedup vs baseline: 2.9359x; 1.0541x over previous
#include <cuda_runtime.h>
#include <cuda_bf16.h>
#include <cstdint>

#define B_ 4
#define H_ 8
#define N_ 2048
#define D_ 64
#define KTOP 16
#define SCALE (1.0f/64.0f)

#define NIT 16              // 512 / BK, BK=32
#define STAGE_BYTES 32768   // A tile 16KB + B tile 16KB
#define NSTAGE 2
#define SMEM_TOTAL (NSTAGE * STAGE_BYTES)   // 64KB -> 2 CTAs/SM

// ---- global scratch (allocation-free rule: __device__ globals) ----
__device__ float g_z[(size_t)B_ * N_ * N_];
// pre-split bf16 planes: [b][h][half][n][64]  (64 = 32 hi bf16 | 32 lo bf16 = 128B)
__device__ __nv_bfloat16 g_qs[(size_t)B_ * H_ * 2 * N_ * 64];
__device__ __nv_bfloat16 g_ks[(size_t)B_ * H_ * 2 * N_ * 64];

// ---------------------------------------------------------------------------
// helpers
// ---------------------------------------------------------------------------
__device__ __forceinline__ uint32_t smem_to_u32(const void* p) {
    uint32_t a;
    asm("{ .reg .u64 t; cvta.to.shared.u64 t, %1; cvt.u32.u64 %0, t; }" : "=r"(a) : "l"(p));
    return a;
}
// tile row = 128B, 8 chunks of 16B; swizzled chunk = chunk ^ (row & 7)
__device__ __forceinline__ uint32_t tile_off(int row, int chunk) {
    return (uint32_t)(row * 128 + ((chunk ^ (row & 7)) << 4));
}
__device__ __forceinline__ void cp16(uint32_t dst, const void* src) {
    asm volatile("cp.async.cg.shared.global [%0], [%1], 16;" :: "r"(dst), "l"(src) : "memory");
}
__device__ __forceinline__ void cp_commit() {
    asm volatile("cp.async.commit_group;" ::: "memory");
}
template<int Ng> __device__ __forceinline__ void cp_wait() {
    asm volatile("cp.async.wait_group %0;" :: "n"(Ng) : "memory");
}
__device__ __forceinline__ void ldsm4(uint32_t* r, uint32_t addr) {
    asm volatile("ldmatrix.sync.aligned.m8n8.x4.shared.b16 {%0,%1,%2,%3}, [%4];"
                 : "=r"(r[0]), "=r"(r[1]), "=r"(r[2]), "=r"(r[3]) : "r"(addr));
}
__device__ __forceinline__ void mma_bf16(float* c, const uint32_t* a,
                                         uint32_t b0, uint32_t b1) {
    asm volatile(
        "mma.sync.aligned.m16n8k16.row.col.f32.bf16.bf16.f32 "
        "{%0,%1,%2,%3}, {%4,%5,%6,%7}, {%8,%9}, {%0,%1,%2,%3};"
        : "+f"(c[0]), "+f"(c[1]), "+f"(c[2]), "+f"(c[3])
        : "r"(a[0]), "r"(a[1]), "r"(a[2]), "r"(a[3]), "r"(b0), "r"(b1));
}
__device__ __forceinline__ float gumbel_of(float u) {
    return -logf(-logf(u + 1e-9f) + 1e-9f);
}

// ---------------------------------------------------------------------------
// Kernel 0: split fp32 -> (hi, lo) bf16 planes in GEMM tile-row format.
// grid (4096, 2): y==0 -> q, y==1 -> k. Each thread: one aligned float4.
// ---------------------------------------------------------------------------
__global__ __launch_bounds__(256) void split_kernel(
    const float* __restrict__ q, const float* __restrict__ k)
{
    const int f = blockIdx.x * 256 + threadIdx.x;       // float4 index
    const size_t e = (size_t)f * 4;
    const int d    = (int)(e & 63);
    const int n    = (int)((e >> 6) & 2047);
    const int hb   = (int)(e >> 17);                    // b*8 + h
    const int half = d >> 5;
    const int pos  = d & 31;

    const float* src = blockIdx.y ? k : q;
    __nv_bfloat16* dst = blockIdx.y ? g_ks : g_qs;

    float4 v = *(const float4*)(src + e);
    const float fv[4] = {v.x, v.y, v.z, v.w};
    ushort hi[4], lo[4];
#pragma unroll
    for (int j = 0; j < 4; j++) {
        __nv_bfloat16 h = __float2bfloat16_rn(fv[j]);
        __nv_bfloat16 l = __float2bfloat16_rn(fv[j] - __bfloat162float(h));
        hi[j] = __bfloat16_as_ushort(h);
        lo[j] = __bfloat16_as_ushort(l);
    }
    __nv_bfloat16* row = dst + ((size_t)(hb * 2 + half) * N_ + n) * 64;
    *(uint2*)((ushort*)row + pos)      = make_uint2(
        (uint32_t)hi[0] | ((uint32_t)hi[1] << 16),
        (uint32_t)hi[2] | ((uint32_t)hi[3] << 16));
    *(uint2*)((ushort*)row + 32 + pos) = make_uint2(
        (uint32_t)lo[0] | ((uint32_t)lo[1] << 16),
        (uint32_t)lo[2] | ((uint32_t)lo[3] << 16));
}

// ---------------------------------------------------------------------------
// Kernel 1: split-bf16 (3-term) mma.sync GEMM + gumbel epilogue -> g_z
// CTA tile 128x128, BK=32, 256 threads = 8 warps (4m x 2n), warp tile 32x64.
// cp.async 2-stage pipeline, 2 CTAs/SM, staged-B register reuse.
// Terms: with bb=B-hi -> hh (ah x bb) AND lh (al x bb); then bb=B-lo -> hl (ah x bb).
// ---------------------------------------------------------------------------
__global__ __launch_bounds__(256, 2) void gemm_mma_kernel(
    const float* __restrict__ u)
{
    extern __shared__ char smem[];
    const uint32_t sbase = smem_to_u32(smem);

    const int tid = threadIdx.x;
    const int lid = tid & 31;
    const int wid = tid >> 5;
    const int wm  = wid >> 1;          // 0..3 : m block (32 rows)
    const int wn  = wid & 1;           // 0..1 : n block (64 cols)

    const int b  = blockIdx.z;
    const int m0 = blockIdx.x * 128;   // z cols (K rows)
    const int n0 = blockIdx.y * 128;   // z rows (Q rows)

    // loader: tid<128 -> A rows (from g_qs), else B rows (from g_ks)
    const int lrow = tid & 127;
    const __nv_bfloat16* lsrc0 = (tid < 128)
        ? g_qs + ((size_t)(b * H_ * 2) * N_ + (n0 + lrow)) * 64
        : g_ks + ((size_t)(b * H_ * 2) * N_ + (m0 + lrow)) * 64;
    const uint32_t my_tile = (tid < 128) ? 0u : 16384u;
    const size_t plane = (size_t)N_ * 64;          // bf16 per (h,half) plane

    float acc[2][8][4];
#pragma unroll
    for (int i = 0; i < 2; i++)
#pragma unroll
        for (int j = 0; j < 8; j++)
#pragma unroll
            for (int t = 0; t < 4; t++) acc[i][j][t] = 0.0f;

    // ldmatrix lane addressing
    const int ar = lid & 15;
    const int ac = lid >> 4;
    const int br = (lid & 7) + ((lid >> 4) << 3);
    const int bc = (lid >> 3) & 1;

    // prologue: stage 0
    {
        const uint32_t dbase = sbase + my_tile;
#pragma unroll
        for (int c = 0; c < 8; c++)
            cp16(dbase + tile_off(lrow, c), (const char*)lsrc0 + c * 16);
        cp_commit();
    }

#pragma unroll 1
    for (int it = 0; it < NIT; it++) {
        const int stg = it & 1;
        cp_wait<0>();          // current stage data landed (issued last iter)
        __syncthreads();       // all reads of the OTHER stage (it-1) done too

        // prefetch next iter into the other stage (now free), overlap compute
        if (it + 1 < NIT) {
            const __nv_bfloat16* src = lsrc0 + (size_t)(it + 1) * plane;
            const uint32_t dbase = sbase + (uint32_t)((1 - stg) * STAGE_BYTES) + my_tile;
#pragma unroll
            for (int c = 0; c < 8; c++)
                cp16(dbase + tile_off(lrow, c), (const char*)src + c * 16);
            cp_commit();
        }

        const uint32_t abase   = sbase + (uint32_t)(stg * STAGE_BYTES);
        const uint32_t bbase_s = abase + 16384u;

#pragma unroll
        for (int s = 0; s < 2; s++) {
            uint32_t ah[2][4], al[2][4], bb[4][4];
#pragma unroll
            for (int mf = 0; mf < 2; mf++) {
                const int arow = wm * 32 + mf * 16 + ar;
                ldsm4(ah[mf], abase + tile_off(arow, s * 2 + ac));
                ldsm4(al[mf], abase + tile_off(arow, s * 2 + ac + 4));
            }
            // --- bb = B-hi: hh term then lh term (32 MMAs total) ---
#pragma unroll
            for (int nf = 0; nf < 4; nf++) {
                const int brow = wn * 64 + nf * 16 + br;
                ldsm4(bb[nf], bbase_s + tile_off(brow, s * 2 + bc));
            }
#pragma unroll
            for (int nf = 0; nf < 4; nf++)
#pragma unroll
                for (int mf = 0; mf < 2; mf++) {
                    mma_bf16(acc[mf][nf * 2 + 0], ah[mf], bb[nf][0], bb[nf][1]);
                    mma_bf16(acc[mf][nf * 2 + 1], ah[mf], bb[nf][2], bb[nf][3]);
                }
#pragma unroll
            for (int nf = 0; nf < 4; nf++)
#pragma unroll
                for (int mf = 0; mf < 2; mf++) {
                    mma_bf16(acc[mf][nf * 2 + 0], al[mf], bb[nf][0], bb[nf][1]);
                    mma_bf16(acc[mf][nf * 2 + 1], al[mf], bb[nf][2], bb[nf][3]);
                }
            // --- bb = B-lo: hl term (16 MMAs) ---
#pragma unroll
            for (int nf = 0; nf < 4; nf++) {
                const int brow = wn * 64 + nf * 16 + br;
                ldsm4(bb[nf], bbase_s + tile_off(brow, s * 2 + bc + 4));
            }
#pragma unroll
            for (int nf = 0; nf < 4; nf++)
#pragma unroll
                for (int mf = 0; mf < 2; mf++) {
                    mma_bf16(acc[mf][nf * 2 + 0], ah[mf], bb[nf][0], bb[nf][1]);
                    mma_bf16(acc[mf][nf * 2 + 1], ah[mf], bb[nf][2], bb[nf][3]);
                }
        }
    }

    // Epilogue: z = acc*SCALE + gumbel(u) -> g_z
    const int r4 = lid >> 2;
    const int c2 = (lid & 3) * 2;
#pragma unroll
    for (int mf = 0; mf < 2; mf++) {
#pragma unroll
        for (int rr = 0; rr < 2; rr++) {
            const int row = n0 + wm * 32 + mf * 16 + r4 + rr * 8;
            const size_t rbase = ((size_t)b * N_ + row) * N_ + m0 + wn * 64;
            const float* urow = u + rbase;
            float*       zrow = g_z + rbase;
#pragma unroll
            for (int j = 0; j < 8; j++) {
                const int co = (j >> 1) * 16 + (j & 1) * 8 + c2;
                float2 uv = *(const float2*)(urow + co);
                float2 zv;
                zv.x = acc[mf][j][rr * 2 + 0] * SCALE + gumbel_of(uv.x);
                zv.y = acc[mf][j][rr * 2 + 1] * SCALE + gumbel_of(uv.y);
                *(float2*)(zrow + co) = zv;
            }
        }
    }
}

// ---------------------------------------------------------------------------
// Kernel 2: exact per-row 16th-largest via register-resident radix select.
// ---------------------------------------------------------------------------
__device__ __forceinline__ uint32_t f2ord(float f) {
    uint32_t v = __float_as_uint(f);
    return (v & 0x80000000u) ? ~v : (v | 0x80000000u);
}

__global__ __launch_bounds__(256) void topk_mask_kernel(float* __restrict__ out)
{
    const int row = blockIdx.x;
    const float* z = g_z + (size_t)row * N_;
    const int tid = threadIdx.x;

    __shared__ int      hist[256];
    __shared__ uint32_t s_prefix;
    __shared__ int      s_k;

    float4 v0 = *(const float4*)(z + tid * 4);
    float4 v1 = *(const float4*)(z + 1024 + tid * 4);
    uint32_t key[8];
    key[0] = f2ord(v0.x); key[1] = f2ord(v0.y); key[2] = f2ord(v0.z); key[3] = f2ord(v0.w);
    key[4] = f2ord(v1.x); key[5] = f2ord(v1.y); key[6] = f2ord(v1.z); key[7] = f2ord(v1.w);

    if (tid == 0) { s_prefix = 0u; s_k = KTOP; }

#pragma unroll
    for (int pass = 0; pass < 4; pass++) {
        const int shift = 24 - pass * 8;
        hist[tid] = 0;
        __syncthreads();
        const uint32_t pref  = s_prefix;
        const int      kneed = s_k;
        const uint32_t hmask = (pass == 0) ? 0u : (0xFFFFFFFFu << (shift + 8));
#pragma unroll
        for (int j = 0; j < 8; j++)
            if ((key[j] & hmask) == pref)
                atomicAdd(&hist[(key[j] >> shift) & 255], 1);
        __syncthreads();

        if (tid < 32) {
            const int base = tid * 8;
            int h[8], ssum = 0;
#pragma unroll
            for (int j = 0; j < 8; j++) { h[j] = hist[base + j]; ssum += h[j]; }
            int suf = ssum;
#pragma unroll
            for (int off = 1; off < 32; off <<= 1) {
                int t = __shfl_down_sync(0xffffffffu, suf, off);
                if (tid + off < 32) suf += t;
            }
            int sufn = __shfl_down_sync(0xffffffffu, suf, 1);
            if (tid == 31) sufn = 0;
            if (suf >= kneed && sufn < kneed) {
                int cum = sufn;
#pragma unroll
                for (int j = 7; j >= 0; j--) {
                    cum += h[j];
                    if (cum >= kneed) {
                        s_prefix = pref | ((uint32_t)(base + j) << shift);
                        s_k      = kneed - (cum - h[j]);
                        break;
                    }
                }
            }
        }
        __syncthreads();
    }

    const uint32_t th = s_prefix;
    float4 o0, o1;
    o0.x = key[0] >= th ? 1.0f : 0.0f;  o0.y = key[1] >= th ? 1.0f : 0.0f;
    o0.z = key[2] >= th ? 1.0f : 0.0f;  o0.w = key[3] >= th ? 1.0f : 0.0f;
    o1.x = key[4] >= th ? 1.0f : 0.0f;  o1.y = key[5] >= th ? 1.0f : 0.0f;
    o1.z = key[6] >= th ? 1.0f : 0.0f;  o1.w = key[7] >= th ? 1.0f : 0.0f;
    *(float4*)(out + (size_t)row * N_ + tid * 4)        = o0;
    *(float4*)(out + (size_t)row * N_ + 1024 + tid * 4) = o1;
}

// ---------------------------------------------------------------------------
extern "C" void kernel_launch(void* const* d_in, const int* in_sizes, int n_in,
                              void* d_out, int out_size)
{
    const float* q = (const float*)d_in[0];
    const float* k = (const float*)d_in[1];
    const float* u = (const float*)d_in[2];
    float* out = (float*)d_out;

    cudaFuncSetAttribute(gemm_mma_kernel,
                         cudaFuncAttributeMaxDynamicSharedMemorySize, SMEM_TOTAL);

    dim3 sgrid(4096, 2);
    split_kernel<<<sgrid, 256>>>(q, k);
    dim3 grid(N_ / 128, N_ / 128, B_);
    gemm_mma_kernel<<<grid, 256, SMEM_TOTAL>>>(u);
    topk_mask_kernel<<<B_ * N_, 256>>>(out);
}

// round 9
// speedup vs baseline: 3.6709x; 1.2503x over previous
#include <cuda_runtime.h>
#include <cuda_bf16.h>
#include <cstdint>

#define B_ 4
#define H_ 8
#define N_ 2048
#define D_ 64
#define KTOP 16
#define SCALE (1.0f/64.0f)
#define MARGIN 0.05f
#define NCAND 64

#define NIT 8               // 512 / BK, BK=64 (one head per iter)
#define STAGE_BYTES 32768   // A tile 16KB + B tile 16KB
#define SMEM_TOTAL (2 * STAGE_BYTES)   // 64KB -> 2 CTAs/SM

// ---- global scratch (allocation-free rule: __device__ globals) ----
__device__ float g_z[(size_t)B_ * N_ * N_];
__device__ __nv_bfloat16 g_qs[(size_t)B_ * H_ * N_ * D_];
__device__ __nv_bfloat16 g_ks[(size_t)B_ * H_ * N_ * D_];

// ---------------------------------------------------------------------------
// helpers
// ---------------------------------------------------------------------------
__device__ __forceinline__ uint32_t smem_to_u32(const void* p) {
    uint32_t a;
    asm("{ .reg .u64 t; cvta.to.shared.u64 t, %1; cvt.u32.u64 %0, t; }" : "=r"(a) : "l"(p));
    return a;
}
// tile row = 128B, 8 chunks of 16B; swizzled chunk = chunk ^ (row & 7)
__device__ __forceinline__ uint32_t tile_off(int row, int chunk) {
    return (uint32_t)(row * 128 + ((chunk ^ (row & 7)) << 4));
}
__device__ __forceinline__ void cp16(uint32_t dst, const void* src) {
    asm volatile("cp.async.cg.shared.global [%0], [%1], 16;" :: "r"(dst), "l"(src) : "memory");
}
__device__ __forceinline__ void cp_commit() {
    asm volatile("cp.async.commit_group;" ::: "memory");
}
template<int Ng> __device__ __forceinline__ void cp_wait() {
    asm volatile("cp.async.wait_group %0;" :: "n"(Ng) : "memory");
}
__device__ __forceinline__ void ldsm4(uint32_t* r, uint32_t addr) {
    asm volatile("ldmatrix.sync.aligned.m8n8.x4.shared.b16 {%0,%1,%2,%3}, [%4];"
                 : "=r"(r[0]), "=r"(r[1]), "=r"(r[2]), "=r"(r[3]) : "r"(addr));
}
__device__ __forceinline__ void mma_bf16(float* c, const uint32_t* a,
                                         uint32_t b0, uint32_t b1) {
    asm volatile(
        "mma.sync.aligned.m16n8k16.row.col.f32.bf16.bf16.f32 "
        "{%0,%1,%2,%3}, {%4,%5,%6,%7}, {%8,%9}, {%0,%1,%2,%3};"
        : "+f"(c[0]), "+f"(c[1]), "+f"(c[2]), "+f"(c[3])
        : "r"(a[0]), "r"(a[1]), "r"(a[2]), "r"(a[3]), "r"(b0), "r"(b1));
}
__device__ __forceinline__ float gumbel_of(float u) {
    return -logf(-logf(u + 1e-9f) + 1e-9f);
}
__device__ __forceinline__ uint32_t pack_bf2(float a, float b) {
    return (uint32_t)__bfloat16_as_ushort(__float2bfloat16_rn(a))
         | ((uint32_t)__bfloat16_as_ushort(__float2bfloat16_rn(b)) << 16);
}

// ---------------------------------------------------------------------------
// Kernel 0: plain fp32 -> bf16 cast (layout preserved).
// grid (2048, 2): y==0 -> q, y==1 -> k. Each thread: 8 elements.
// ---------------------------------------------------------------------------
__global__ __launch_bounds__(256) void convert_kernel(
    const float* __restrict__ q, const float* __restrict__ k)
{
    const size_t e = ((size_t)blockIdx.x * 256 + threadIdx.x) * 8;
    const float* src = blockIdx.y ? k : q;
    __nv_bfloat16* dst = blockIdx.y ? g_ks : g_qs;
    float4 a = *(const float4*)(src + e);
    float4 b = *(const float4*)(src + e + 4);
    uint4 o;
    o.x = pack_bf2(a.x, a.y);
    o.y = pack_bf2(a.z, a.w);
    o.z = pack_bf2(b.x, b.y);
    o.w = pack_bf2(b.z, b.w);
    *(uint4*)(dst + e) = o;
}

// ---------------------------------------------------------------------------
// Kernel 1: 1-term bf16 mma.sync GEMM + gumbel -> z_approx in g_z.
// CTA tile 128x128, BK=64 (one head/iter), 256 threads = 8 warps (4m x 2n).
// cp.async 2-stage pipeline, 2 CTAs/SM.
// ---------------------------------------------------------------------------
__global__ __launch_bounds__(256, 2) void gemm_approx_kernel(
    const float* __restrict__ u)
{
    extern __shared__ char smem[];
    const uint32_t sbase = smem_to_u32(smem);

    const int tid = threadIdx.x;
    const int lid = tid & 31;
    const int wid = tid >> 5;
    const int wm  = wid >> 1;          // 0..3 : m block (32 rows)
    const int wn  = wid & 1;           // 0..1 : n block (64 cols)

    const int b  = blockIdx.z;
    const int m0 = blockIdx.x * 128;   // z cols (K rows)
    const int n0 = blockIdx.y * 128;   // z rows (Q rows)

    // loader: tid<128 -> A rows (g_qs), else B rows (g_ks); one 128B row each
    const int lrow = tid & 127;
    const __nv_bfloat16* lsrc0 = (tid < 128)
        ? g_qs + ((size_t)(b * H_) * N_ + (n0 + lrow)) * D_
        : g_ks + ((size_t)(b * H_) * N_ + (m0 + lrow)) * D_;
    const uint32_t my_tile = (tid < 128) ? 0u : 16384u;
    const size_t plane = (size_t)N_ * D_;          // bf16 per head plane

    float acc[2][8][4];
#pragma unroll
    for (int i = 0; i < 2; i++)
#pragma unroll
        for (int j = 0; j < 8; j++)
#pragma unroll
            for (int t = 0; t < 4; t++) acc[i][j][t] = 0.0f;

    // ldmatrix lane addressing
    const int ar = lid & 15;
    const int ac = lid >> 4;
    const int br = (lid & 7) + ((lid >> 4) << 3);
    const int bc = (lid >> 3) & 1;

    // prologue: stage 0
    {
        const uint32_t dbase = sbase + my_tile;
#pragma unroll
        for (int c = 0; c < 8; c++)
            cp16(dbase + tile_off(lrow, c), (const char*)lsrc0 + c * 16);
        cp_commit();
    }

#pragma unroll 1
    for (int it = 0; it < NIT; it++) {
        const int stg = it & 1;
        cp_wait<0>();
        __syncthreads();

        if (it + 1 < NIT) {
            const __nv_bfloat16* src = lsrc0 + (size_t)(it + 1) * plane;
            const uint32_t dbase = sbase + (uint32_t)((1 - stg) * STAGE_BYTES) + my_tile;
#pragma unroll
            for (int c = 0; c < 8; c++)
                cp16(dbase + tile_off(lrow, c), (const char*)src + c * 16);
            cp_commit();
        }

        const uint32_t abase   = sbase + (uint32_t)(stg * STAGE_BYTES);
        const uint32_t bbase_s = abase + 16384u;

#pragma unroll
        for (int s = 0; s < 4; s++) {          // 4 k16 steps per BK=64
            uint32_t ah[2][4], bb[4][4];
#pragma unroll
            for (int mf = 0; mf < 2; mf++) {
                const int arow = wm * 32 + mf * 16 + ar;
                ldsm4(ah[mf], abase + tile_off(arow, s * 2 + ac));
            }
#pragma unroll
            for (int nf = 0; nf < 4; nf++) {
                const int brow = wn * 64 + nf * 16 + br;
                ldsm4(bb[nf], bbase_s + tile_off(brow, s * 2 + bc));
            }
#pragma unroll
            for (int nf = 0; nf < 4; nf++)
#pragma unroll
                for (int mf = 0; mf < 2; mf++) {
                    mma_bf16(acc[mf][nf * 2 + 0], ah[mf], bb[nf][0], bb[nf][1]);
                    mma_bf16(acc[mf][nf * 2 + 1], ah[mf], bb[nf][2], bb[nf][3]);
                }
        }
    }

    // Epilogue: z_approx = acc*SCALE + gumbel(u) -> g_z
    const int r4 = lid >> 2;
    const int c2 = (lid & 3) * 2;
#pragma unroll
    for (int mf = 0; mf < 2; mf++) {
#pragma unroll
        for (int rr = 0; rr < 2; rr++) {
            const int row = n0 + wm * 32 + mf * 16 + r4 + rr * 8;
            const size_t rbase = ((size_t)b * N_ + row) * N_ + m0 + wn * 64;
            const float* urow = u + rbase;
            float*       zrow = g_z + rbase;
#pragma unroll
            for (int j = 0; j < 8; j++) {
                const int co = (j >> 1) * 16 + (j & 1) * 8 + c2;
                float2 uv = *(const float2*)(urow + co);
                float2 zv;
                zv.x = acc[mf][j][rr * 2 + 0] * SCALE + gumbel_of(uv.x);
                zv.y = acc[mf][j][rr * 2 + 1] * SCALE + gumbel_of(uv.y);
                *(float2*)(zrow + co) = zv;
            }
        }
    }
}

// ---------------------------------------------------------------------------
// Kernel 2: radix-select on z_approx -> candidate set within MARGIN ->
// exact fp32 recompute of candidates -> exact 16th-largest -> mask.
// One block (256 threads) per row.
// ---------------------------------------------------------------------------
__device__ __forceinline__ uint32_t f2ord(float f) {
    uint32_t v = __float_as_uint(f);
    return (v & 0x80000000u) ? ~v : (v | 0x80000000u);
}
__device__ __forceinline__ float ord2f(uint32_t o) {
    uint32_t v = (o & 0x80000000u) ? (o & 0x7FFFFFFFu) : ~o;
    return __uint_as_float(v);
}

__global__ __launch_bounds__(256) void topk_refine_kernel(
    const float* __restrict__ q, const float* __restrict__ k,
    const float* __restrict__ u, float* __restrict__ out)
{
    const int row = blockIdx.x;            // b*2048 + n
    const int b = row >> 11;
    const int n = row & 2047;
    const int tid = threadIdx.x;
    const int lid = tid & 31, wid = tid >> 5;

    __shared__ int      hist[256];
    __shared__ uint32_t s_prefix;
    __shared__ int      s_k;
    __shared__ float    qs[512];
    __shared__ int      scols[NCAND];
    __shared__ float    cand_z[NCAND];
    __shared__ int      scount;
    __shared__ float    s_thresh;

    const float* z = g_z + (size_t)row * N_;
    float4 v0 = *(const float4*)(z + tid * 4);
    float4 v1 = *(const float4*)(z + 1024 + tid * 4);
    float vals[8] = {v0.x, v0.y, v0.z, v0.w, v1.x, v1.y, v1.z, v1.w};
    uint32_t key[8];
#pragma unroll
    for (int j = 0; j < 8; j++) key[j] = f2ord(vals[j]);

    // load q row (512 floats over 8 heads) into smem
    {
        int c = tid;
        qs[c] = q[(((size_t)(b * H_ + (c >> 6)) * N_ + n) << 6) + (c & 63)];
        c = tid + 256;
        qs[c] = q[(((size_t)(b * H_ + (c >> 6)) * N_ + n) << 6) + (c & 63)];
    }
    if (tid == 0) { s_prefix = 0u; s_k = KTOP; scount = 0; }

    // exact 16th-largest of z_approx via radix select
#pragma unroll
    for (int pass = 0; pass < 4; pass++) {
        const int shift = 24 - pass * 8;
        hist[tid] = 0;
        __syncthreads();
        const uint32_t pref  = s_prefix;
        const int      kneed = s_k;
        const uint32_t hmask = (pass == 0) ? 0u : (0xFFFFFFFFu << (shift + 8));
#pragma unroll
        for (int j = 0; j < 8; j++)
            if ((key[j] & hmask) == pref)
                atomicAdd(&hist[(key[j] >> shift) & 255], 1);
        __syncthreads();

        if (tid < 32) {
            const int base = tid * 8;
            int h[8], ssum = 0;
#pragma unroll
            for (int j = 0; j < 8; j++) { h[j] = hist[base + j]; ssum += h[j]; }
            int suf = ssum;
#pragma unroll
            for (int off = 1; off < 32; off <<= 1) {
                int t = __shfl_down_sync(0xffffffffu, suf, off);
                if (tid + off < 32) suf += t;
            }
            int sufn = __shfl_down_sync(0xffffffffu, suf, 1);
            if (tid == 31) sufn = 0;
            if (suf >= kneed && sufn < kneed) {
                int cum = sufn;
#pragma unroll
                for (int j = 7; j >= 0; j--) {
                    cum += h[j];
                    if (cum >= kneed) {
                        s_prefix = pref | ((uint32_t)(base + j) << shift);
                        s_k      = kneed - (cum - h[j]);
                        break;
                    }
                }
            }
        }
        __syncthreads();
    }

    const float thr_lo = ord2f(s_prefix) - MARGIN;

    // candidate collect (cols whose approx z is within margin of threshold)
#pragma unroll
    for (int j = 0; j < 8; j++) {
        if (vals[j] >= thr_lo) {
            const int col = (j < 4) ? (tid * 4 + j) : (1024 + tid * 4 + (j - 4));
            int i = atomicAdd(&scount, 1);
            if (i < NCAND) scols[i] = col;
        }
    }
    __syncthreads();
    const int count = (scount < NCAND) ? scount : NCAND;

    // exact fp32 recompute per candidate (one warp per candidate)
    const float* kb = k + (size_t)(b * H_) * N_ * D_;
    for (int i = wid; i < count; i += 8) {
        const int m = scols[i];
        float sum = 0.0f;
#pragma unroll
        for (int t = 0; t < 16; t++) {
            const int c = lid + 32 * t;
            sum += qs[c] * kb[(((size_t)(c >> 6) * N_ + m) << 6) + (c & 63)];
        }
#pragma unroll
        for (int off = 16; off; off >>= 1)
            sum += __shfl_xor_sync(0xffffffffu, sum, off);
        if (lid == 0)
            cand_z[i] = sum * SCALE + gumbel_of(u[(size_t)row * N_ + m]);
    }
    __syncthreads();

    // exact 16th-largest among candidates (warp 0, O(count^2) rank method)
    if (wid == 0) {
        float va = (lid < count) ? cand_z[lid] : -1e30f;
        float vb = (32 + lid < count) ? cand_z[32 + lid] : -1e30f;
        int ca = 0, cb = 0;
        for (int j = 0; j < count; j++) {
            const float w = cand_z[j];
            ca += (w >= va);
            cb += (w >= vb);
        }
        float t1 = (ca >= KTOP && lid < count) ? va : -1e30f;
        float t2 = (cb >= KTOP && 32 + lid < count) ? vb : -1e30f;
        float mx = fmaxf(t1, t2);
#pragma unroll
        for (int off = 16; off; off >>= 1)
            mx = fmaxf(mx, __shfl_xor_sync(0xffffffffu, mx, off));
        if (lid == 0) s_thresh = mx;
    }
    __syncthreads();
    const float thr = s_thresh;

    // mask: zeros except candidates with exact z >= exact threshold
    float mk[8] = {0, 0, 0, 0, 0, 0, 0, 0};
    for (int i = 0; i < count; i++) {
        if (cand_z[i] >= thr) {
            const int c = scols[i];
            const int rel  = c - tid * 4;
            if (rel >= 0 && rel < 4) mk[rel] = 1.0f;
            const int rel2 = c - 1024 - tid * 4;
            if (rel2 >= 0 && rel2 < 4) mk[4 + rel2] = 1.0f;
        }
    }
    float* o = out + (size_t)row * N_;
    *(float4*)(o + tid * 4)        = make_float4(mk[0], mk[1], mk[2], mk[3]);
    *(float4*)(o + 1024 + tid * 4) = make_float4(mk[4], mk[5], mk[6], mk[7]);
}

// ---------------------------------------------------------------------------
extern "C" void kernel_launch(void* const* d_in, const int* in_sizes, int n_in,
                              void* d_out, int out_size)
{
    const float* q = (const float*)d_in[0];
    const float* k = (const float*)d_in[1];
    const float* u = (const float*)d_in[2];
    float* out = (float*)d_out;

    cudaFuncSetAttribute(gemm_approx_kernel,
                         cudaFuncAttributeMaxDynamicSharedMemorySize, SMEM_TOTAL);

    dim3 cgrid(2048, 2);
    convert_kernel<<<cgrid, 256>>>(q, k);
    dim3 grid(N_ / 128, N_ / 128, B_);
    gemm_approx_kernel<<<grid, 256, SMEM_TOTAL>>>(u);
    topk_refine_kernel<<<B_ * N_, 256>>>(q, k, u, out);
}